// round 1
// baseline (speedup 1.0000x reference)
#include <cuda_runtime.h>
#include <math.h>

#define Bn 2
#define C 32
#define H 256
#define W 512
#define LH 64
#define LW 128

// Scratch (no allocations allowed): P[b][ly][lx][o] = W0_lr @ lr
__device__ float g_P[Bn * LH * LW * 32];
// dtable[k][py][px][o] = W0_d @ d_k(py,px)
__device__ float g_dt[9 * 4 * 4 * 32];

// ---------------------------------------------------------------------------
// Kernel 1: P[b,ly,lx,o] = sum_c w0[o,c] * lr[b,c,ly,lx]   (c in 0..31)
// One thread computes 8 outputs for one lr pixel.
// ---------------------------------------------------------------------------
__global__ __launch_bounds__(256) void k_precompute_P(
    const float* __restrict__ lr, const float* __restrict__ w0)
{
    __shared__ float sw[32 * 32];  // sw[c*32+o] = w0[o*66 + c]
    int t = threadIdx.x;
    for (int i = t; i < 32 * 32; i += 256) {
        int c = i >> 5, o = i & 31;
        sw[i] = w0[o * 66 + c];
        (void)c;
    }
    __syncthreads();

    int gid = blockIdx.x * 256 + t;
    int pix = gid >> 2;            // (b,ly,lx) flattened
    int og  = (gid & 3) * 8;       // output group of 8
    if (pix >= Bn * LH * LW) return;
    int b   = pix / (LH * LW);
    int rem = pix - b * (LH * LW);

    const float* lp = lr + (size_t)b * C * LH * LW + rem;
    float acc[8];
#pragma unroll
    for (int o = 0; o < 8; o++) acc[o] = 0.f;
#pragma unroll
    for (int c = 0; c < 32; c++) {
        float v = lp[c * (LH * LW)];
#pragma unroll
        for (int o = 0; o < 8; o++)
            acc[o] = fmaf(v, sw[c * 32 + og + o], acc[o]);
    }
    float* P = g_P + (size_t)pix * 32 + og;
#pragma unroll
    for (int o = 0; o < 8; o++) P[o] = acc[o];
}

// ---------------------------------------------------------------------------
// Kernel 2: distance-matrix contribution table.
// base = {-2,-1,1,2}; k0: (bx,by); k1/k5: (4-px, by); k2/k6: (px+1, by);
// k3/k7: (bx, 4-py); k4/k8: (bx, py+1)
// ---------------------------------------------------------------------------
__global__ void k_precompute_dt(const float* __restrict__ w0)
{
    int t = blockIdx.x * blockDim.x + threadIdx.x;
    if (t >= 9 * 4 * 4 * 32) return;
    int o  = t & 31;
    int px = (t >> 5) & 3;
    int py = (t >> 7) & 3;
    int k  = t >> 9;

    const float base[4] = {-2.f, -1.f, 1.f, 2.f};
    float bx = base[px], by = base[py];
    float d0, d1;
    if (k == 0)                { d0 = bx;            d1 = by;            }
    else if (k == 1 || k == 5) { d0 = 4.f - (float)px; d1 = by;          }
    else if (k == 2 || k == 6) { d0 = (float)px + 1.f; d1 = by;          }
    else if (k == 3 || k == 7) { d0 = bx;            d1 = 4.f - (float)py; }
    else                       { d0 = bx;            d1 = (float)py + 1.f; }

    g_dt[t] = w0[o * 66 + 64] * d0 + w0[o * 66 + 65] * d1;
}

// ---------------------------------------------------------------------------
// Kernel 3: main. Tile = 64 wide x 4 tall, 256 threads, 1 pixel/thread.
// Writes 9 logit channels to out (softmax done by kernel 4).
// ---------------------------------------------------------------------------
__global__ __launch_bounds__(256) void k_main(
    const float* __restrict__ hr,
    const float* __restrict__ w1,
    const float* __restrict__ w2,
    const float* __restrict__ w3,
    const float* __restrict__ w0,
    float* __restrict__ out)
{
    __shared__ float sW0hr[32 * 32];   // [c][o]
    __shared__ float sW1[32 * 16];     // [c][o]
    __shared__ float sW2[16 * 8];      // [c][o]
    __shared__ float sW3[8];
    __shared__ float sDT[9 * 16 * 32];
    __shared__ float sP[3 * 18 * 32];  // ly -1..+1, lx -1..+16 halo

    const int tid = threadIdx.x;
    const int x0  = blockIdx.x * 64;
    const int y0  = blockIdx.y * 4;
    const int b   = blockIdx.z;
    const int lx0 = x0 >> 2, ly0 = y0 >> 2;

    // cooperative shared loads
    for (int i = tid; i < 32 * 32; i += 256) {
        int c = i >> 5, o = i & 31;
        sW0hr[i] = w0[o * 66 + 32 + c];
    }
    for (int i = tid; i < 32 * 16; i += 256) {
        int c = i >> 4, o = i & 15;
        sW1[i] = w1[o * 32 + c];
    }
    for (int i = tid; i < 16 * 8; i += 256) {
        int c = i >> 3, o = i & 7;
        sW2[i] = w2[o * 16 + c];
    }
    if (tid < 8) sW3[tid] = w3[tid];
    for (int i = tid; i < 9 * 16 * 32; i += 256) sDT[i] = g_dt[i];
    for (int i = tid; i < 3 * 18 * 32; i += 256) {
        int o   = i & 31;
        int lxl = (i >> 5) % 18;
        int lyl = i / (32 * 18);
        int glx = min(max(lx0 - 1 + lxl, 0), LW - 1);
        int gly = min(max(ly0 - 1 + lyl, 0), LH - 1);
        sP[i] = g_P[(((size_t)b * LH + gly) * LW + glx) * 32 + o];
    }
    __syncthreads();

    const int x  = x0 + (tid & 63);
    const int y  = y0 + (tid >> 6);
    const int px = x & 3, py = y & 3;

    // hr-part of layer 0 (shared by all 9 directions)
    const float* hp = hr + ((size_t)b * C * H + y) * W + x;
    float hpart[32];
#pragma unroll
    for (int o = 0; o < 32; o++) hpart[o] = 0.f;
#pragma unroll
    for (int c = 0; c < 32; c++) {
        float v = hp[(size_t)c * H * W];
#pragma unroll
        for (int o = 0; o < 32; o++)
            hpart[o] = fmaf(v, sW0hr[c * 32 + o], hpart[o]);
    }

    float* outp = out + ((size_t)b * 9 * H + y) * W + x;

    // bitmasks: dy=-1 for k in {3,5,6}, dy=+1 for {4,7,8};
    //           dx=-1 for {1,5,7},     dx=+1 for {2,6,8}
    const unsigned NY = (1u<<3)|(1u<<5)|(1u<<6), PY = (1u<<4)|(1u<<7)|(1u<<8);
    const unsigned NX = (1u<<1)|(1u<<5)|(1u<<7), PX = (1u<<2)|(1u<<6)|(1u<<8);

    for (int k = 0; k < 9; k++) {
        int dy = (int)((PY >> k) & 1u) - (int)((NY >> k) & 1u);
        int dx = (int)((PX >> k) & 1u) - (int)((NX >> k) & 1u);
        int xn = x + dx * 4, yn = y + dy * 4;
        bool valid = (xn >= 0) & (xn < W) & (yn >= 0) & (yn < H);

        int lxl = ((x >> 2) - lx0) + 1 + dx;   // 0..17
        int lyl = ((y >> 2) - ly0) + 1 + dy;   // 0..2
        const float* Pn = &sP[(lyl * 18 + lxl) * 32];
        const float* dt = &sDT[((k * 4 + py) * 4 + px) * 32];

        float h0[32];
#pragma unroll
        for (int o = 0; o < 32; o++) {
            float v = hpart[o] + Pn[o] + dt[o];
            h0[o] = fmaxf(v, 0.01f * v);        // LeakyReLU(0.01)
        }

        float h1[16];
#pragma unroll
        for (int j = 0; j < 16; j++) h1[j] = 0.f;
#pragma unroll
        for (int c = 0; c < 32; c++) {
#pragma unroll
            for (int j = 0; j < 16; j++)
                h1[j] = fmaf(h0[c], sW1[c * 16 + j], h1[j]);
        }
#pragma unroll
        for (int j = 0; j < 16; j++) h1[j] = fmaxf(h1[j], 0.01f * h1[j]);

        float h2[8];
#pragma unroll
        for (int j = 0; j < 8; j++) h2[j] = 0.f;
#pragma unroll
        for (int c = 0; c < 16; c++) {
#pragma unroll
            for (int j = 0; j < 8; j++)
                h2[j] = fmaf(h1[c], sW2[c * 8 + j], h2[j]);
        }

        float logit = 0.f;
#pragma unroll
        for (int c = 0; c < 8; c++)
            logit = fmaf(fmaxf(h2[c], 0.01f * h2[c]), sW3[c], logit);

        outp[(size_t)k * H * W] = valid ? logit : -100.0f;
    }
}

// ---------------------------------------------------------------------------
// Kernel 4: in-place softmax over the 9 channels.
// ---------------------------------------------------------------------------
__global__ __launch_bounds__(256) void k_softmax(float* __restrict__ out)
{
    int i = blockIdx.x * 256 + threadIdx.x;   // over b*H*W
    if (i >= Bn * H * W) return;
    int b  = i / (H * W);
    int yx = i - b * (H * W);
    float* p = out + (size_t)b * 9 * H * W + yx;

    float v[9], m = -1e30f;
#pragma unroll
    for (int k = 0; k < 9; k++) {
        v[k] = p[(size_t)k * H * W];
        m = fmaxf(m, v[k]);
    }
    float s = 0.f;
#pragma unroll
    for (int k = 0; k < 9; k++) {
        v[k] = expf(v[k] - m);
        s += v[k];
    }
    float inv = 1.f / s;
#pragma unroll
    for (int k = 0; k < 9; k++) p[(size_t)k * H * W] = v[k] * inv;
}

// ---------------------------------------------------------------------------
extern "C" void kernel_launch(void* const* d_in, const int* in_sizes, int n_in,
                              void* d_out, int out_size)
{
    const float* lr = (const float*)d_in[0];
    const float* hr = (const float*)d_in[1];
    // d_in[2], d_in[3] (lr_feature_r / hr_feature_r) are unused by the reference
    const float* w0 = (const float*)d_in[4];
    const float* w1 = (const float*)d_in[5];
    const float* w2 = (const float*)d_in[6];
    const float* w3 = (const float*)d_in[7];
    float* out = (float*)d_out;

    k_precompute_P<<<(Bn * LH * LW * 4 + 255) / 256, 256>>>(lr, w0);
    k_precompute_dt<<<(9 * 4 * 4 * 32 + 255) / 256, 256>>>(w0);

    dim3 grid(W / 64, H / 4, Bn);
    k_main<<<grid, 256>>>(hr, w1, w2, w3, w0, out);

    k_softmax<<<(Bn * H * W + 255) / 256, 256>>>(out);
}

// round 2
// speedup vs baseline: 1.0153x; 1.0153x over previous
#include <cuda_runtime.h>
#include <math.h>

#define Bn 2
#define C 32
#define H 256
#define W 512
#define LH 64
#define LW 128

// ---------------------------------------------------------------------------
// Single fused kernel.
// Tile = 64 wide x 4 tall, 256 threads, 1 pixel/thread.
// Per block:
//   - load all weights to shared
//   - build dt table (9 dirs x 4x4 phase x 32 out) in shared
//   - build P halo (W0_lr @ lr for the 3x18 lr pixels this tile can touch)
//   - per pixel: hr-part of layer0 once, then 9 directions through the MLP,
//     softmax over the 9 logits in registers, 9 coalesced stores.
// ---------------------------------------------------------------------------
__global__ __launch_bounds__(256, 2) void k_fused(
    const float* __restrict__ lr,
    const float* __restrict__ hr,
    const float* __restrict__ w0,
    const float* __restrict__ w1,
    const float* __restrict__ w2,
    const float* __restrict__ w3,
    float* __restrict__ out)
{
    __shared__ float sW0lr[32 * 32];   // [c][o]
    __shared__ float sW0hr[32 * 32];   // [c][o]
    __shared__ float sW1[32 * 16];     // [c][o]
    __shared__ float sW2[16 * 8];      // [c][o]
    __shared__ float sW3[8];
    __shared__ float sDT[9 * 16 * 32]; // [k][py*4+px][o]
    __shared__ float sP[3 * 18 * 32];  // [ly -1..+1][lx -1..+16][o]

    const int tid = threadIdx.x;
    const int x0  = blockIdx.x * 64;
    const int y0  = blockIdx.y * 4;
    const int b   = blockIdx.z;
    const int lx0 = x0 >> 2, ly0 = y0 >> 2;

    // ---- stage weights ----
    for (int i = tid; i < 32 * 32; i += 256) {
        int c = i >> 5, o = i & 31;
        sW0lr[i] = w0[o * 66 + c];
        sW0hr[i] = w0[o * 66 + 32 + c];
    }
    for (int i = tid; i < 32 * 16; i += 256) {
        int c = i >> 4, o = i & 15;
        sW1[i] = w1[o * 32 + c];
    }
    for (int i = tid; i < 16 * 8; i += 256) {
        int c = i >> 3, o = i & 7;
        sW2[i] = w2[o * 16 + c];
    }
    if (tid < 8) sW3[tid] = w3[tid];

    // ---- dt table: W0_d @ d_k(py,px) ----
    for (int i = tid; i < 9 * 16 * 32; i += 256) {
        int o  = i & 31;
        int px = (i >> 5) & 3;
        int py = (i >> 7) & 3;
        int k  = i >> 9;
        const float base[4] = {-2.f, -1.f, 1.f, 2.f};
        float bx = base[px], by = base[py];
        float d0, d1;
        if (k == 0)                { d0 = bx;              d1 = by;              }
        else if (k == 1 || k == 5) { d0 = 4.f - (float)px; d1 = by;              }
        else if (k == 2 || k == 6) { d0 = (float)px + 1.f; d1 = by;              }
        else if (k == 3 || k == 7) { d0 = bx;              d1 = 4.f - (float)py; }
        else                       { d0 = bx;              d1 = (float)py + 1.f; }
        sDT[i] = w0[o * 66 + 64] * d0 + w0[o * 66 + 65] * d1;
    }
    __syncthreads();

    // ---- P halo: 54 lr pixels x 32 outputs, 4 threads per pixel ----
    if (tid < 216) {
        int pix = tid >> 2;            // 0..53
        int og  = (tid & 3) * 8;
        int lxl = pix % 18, lyl = pix / 18;
        int glx = min(max(lx0 - 1 + lxl, 0), LW - 1);
        int gly = min(max(ly0 - 1 + lyl, 0), LH - 1);
        const float* lp = lr + ((size_t)(b * C) * LH + gly) * LW + glx;
        float acc[8];
#pragma unroll
        for (int o = 0; o < 8; o++) acc[o] = 0.f;
#pragma unroll
        for (int c = 0; c < 32; c++) {
            float v = lp[(size_t)c * LH * LW];
#pragma unroll
            for (int o = 0; o < 8; o++)
                acc[o] = fmaf(v, sW0lr[c * 32 + og + o], acc[o]);
        }
        float* Pd = &sP[(lyl * 18 + lxl) * 32 + og];
#pragma unroll
        for (int o = 0; o < 8; o++) Pd[o] = acc[o];
    }
    __syncthreads();

    // ---- per-pixel compute ----
    const int x  = x0 + (tid & 63);
    const int y  = y0 + (tid >> 6);
    const int px = x & 3, py = y & 3;

    // hr-part of layer 0 (shared by all 9 directions)
    const float* hp = hr + ((size_t)b * C * H + y) * W + x;
    float hpart[32];
#pragma unroll
    for (int o = 0; o < 32; o++) hpart[o] = 0.f;
#pragma unroll
    for (int c = 0; c < 32; c++) {
        float v = hp[(size_t)c * H * W];
#pragma unroll
        for (int o = 0; o < 32; o++)
            hpart[o] = fmaf(v, sW0hr[c * 32 + o], hpart[o]);
    }

    // direction offsets: dy=-1 for k in {3,5,6}, dy=+1 for {4,7,8};
    //                    dx=-1 for {1,5,7},     dx=+1 for {2,6,8}
    const unsigned NY = (1u<<3)|(1u<<5)|(1u<<6), PY = (1u<<4)|(1u<<7)|(1u<<8);
    const unsigned NX = (1u<<1)|(1u<<5)|(1u<<7), PX = (1u<<2)|(1u<<6)|(1u<<8);

    float v9[9];

#pragma unroll 1
    for (int k = 0; k < 9; k++) {
        int dy = (int)((PY >> k) & 1u) - (int)((NY >> k) & 1u);
        int dx = (int)((PX >> k) & 1u) - (int)((NX >> k) & 1u);
        int xn = x + dx * 4, yn = y + dy * 4;
        bool valid = (xn >= 0) & (xn < W) & (yn >= 0) & (yn < H);

        int lxl = ((x >> 2) - lx0) + 1 + dx;   // 0..17
        int lyl = 1 + dy;                      // 0..2 (tile is 4 rows = 1 lr row)
        const float* Pn = &sP[(lyl * 18 + lxl) * 32];
        const float* dt = &sDT[((k * 4 + py) * 4 + px) * 32];

        float h0[32];
#pragma unroll
        for (int o = 0; o < 32; o++) {
            float t = hpart[o] + Pn[o] + dt[o];
            h0[o] = fmaxf(t, 0.01f * t);        // LeakyReLU(0.01)
        }

        float h1[16];
#pragma unroll
        for (int j = 0; j < 16; j++) h1[j] = 0.f;
#pragma unroll
        for (int c = 0; c < 32; c++) {
#pragma unroll
            for (int j = 0; j < 16; j++)
                h1[j] = fmaf(h0[c], sW1[c * 16 + j], h1[j]);
        }
#pragma unroll
        for (int j = 0; j < 16; j++) h1[j] = fmaxf(h1[j], 0.01f * h1[j]);

        float h2[8];
#pragma unroll
        for (int j = 0; j < 8; j++) h2[j] = 0.f;
#pragma unroll
        for (int c = 0; c < 16; c++) {
#pragma unroll
            for (int j = 0; j < 8; j++)
                h2[j] = fmaf(h1[c], sW2[c * 8 + j], h2[j]);
        }

        float logit = 0.f;
#pragma unroll
        for (int c = 0; c < 8; c++)
            logit = fmaf(fmaxf(h2[c], 0.01f * h2[c]), sW3[c], logit);

        v9[k] = valid ? logit : -100.0f;
    }

    // ---- fused softmax over the 9 logits ----
    float m = v9[0];
#pragma unroll
    for (int k = 1; k < 9; k++) m = fmaxf(m, v9[k]);
    float s = 0.f;
#pragma unroll
    for (int k = 0; k < 9; k++) {
        v9[k] = __expf(v9[k] - m);
        s += v9[k];
    }
    float inv = 1.f / s;

    float* outp = out + ((size_t)b * 9 * H + y) * W + x;
#pragma unroll
    for (int k = 0; k < 9; k++)
        outp[(size_t)k * H * W] = v9[k] * inv;
}

// ---------------------------------------------------------------------------
extern "C" void kernel_launch(void* const* d_in, const int* in_sizes, int n_in,
                              void* d_out, int out_size)
{
    const float* lr = (const float*)d_in[0];
    const float* hr = (const float*)d_in[1];
    // d_in[2], d_in[3] (lr_feature_r / hr_feature_r) are unused by the reference
    const float* w0 = (const float*)d_in[4];
    const float* w1 = (const float*)d_in[5];
    const float* w2 = (const float*)d_in[6];
    const float* w3 = (const float*)d_in[7];
    float* out = (float*)d_out;

    dim3 grid(W / 64, H / 4, Bn);
    k_fused<<<grid, 256>>>(lr, hr, w0, w1, w2, w3, out);
}